// round 9
// baseline (speedup 1.0000x reference)
#include <cuda_runtime.h>
#include <cuda_fp16.h>

#define DD 160
#define HH 192
#define WW 224
#define VV (DD*HH*WW)        // 6881280
#define W4 (WW/4)            // 56 float4 per row

#define TW 28                // tile width (voxels)
#define TG 7                 // uint2 (4-half) groups per tile row
#define TH 16                // tile height
#define RR 24                // raw rows (TH + 8)
#define RSTF 44              // raw smem stride in floats (conflict-free)
#define SST 9                // W-sum smem stride in uint2
#define RING 10              // D-window ring depth
#define DC 40                // D outputs per block
#define NP (DC + 8)          // planes processed per block

#define SW_F (RR * SST)      // uint2 per field in sW = 216
#define OFF_RJ (RR * RSTF)                                  // 1056 floats
#define SMEM_BYTES (RR*RSTF*4*2 + 5*RR*SST*8 + RING*5*112*8 + 32)  // 61920

union U2H4 { uint2 u; __half2 h[2]; };

__device__ __forceinline__ float cc1(float si, float sj, float si2, float sj2, float sij) {
    const float inv = 1.0f / 729.0f;
    float cross = sij - si * sj * inv;
    float ivar  = si2 - si * si * inv;
    float jvar  = sj2 - sj * sj * inv;
    return __fdividef(cross * cross, ivar * jvar + 1e-5f);
}

// ---------------------------------------------------------------------------
// Fully fused NCC: W-sum + H-sum + D-window + cc + mean in ONE kernel.
// Block marches a 28x16 tile through 48 d-planes with a 10-plane smem ring.
// ---------------------------------------------------------------------------
__global__ void __launch_bounds__(256, 3) fused(const float* __restrict__ I,
                                                const float* __restrict__ J,
                                                float* __restrict__ out) {
    extern __shared__ __align__(16) char smem[];
    float* sRI   = (float*)smem;                                   // 4224 B
    float* sRJ   = sRI + OFF_RJ;                                   // 4224 B
    uint2* sW    = (uint2*)(smem + RR*RSTF*4*2);                   // 8640 B
    uint2* sRing = (uint2*)(smem + RR*RSTF*4*2 + 5*RR*SST*8);      // 44800 B
    float* wred  = (float*)(smem + RR*RSTF*4*2 + 5*RR*SST*8 + RING*5*112*8);

    const int tid   = threadIdx.x;
    const int h0    = blockIdx.y * TH;
    const int dout0 = blockIdx.z * DC;
    const int fbase = 7 * (int)blockIdx.x - 1;      // first f4 col (w0-4)/4

    // raw-load role: 216 items = 24 rows x 9 f4-cols
    const bool ldr = (tid < 216);
    const int  lr  = tid / 9, lc = tid - lr * 9;
    const int  gh  = h0 - 4 + lr;
    const int  gf  = fbase + lc;
    const bool inb = ldr && (gh >= 0) && (gh < HH) && (gf >= 0) && (gf < W4);
    const unsigned pq = inb ? (unsigned)(gh * W4 + gf) : 0u;
    const int  sroff = lr * RSTF + 4 * lc;

    // phase1 role: 168 items = 7 groups x 24 rows
    const bool p1 = (tid < 168);
    const int  p1g = tid / 24, p1r = tid - p1g * 24;
    // phase2 role: 140 units = 5 fields x 4 segs x 7 cols
    const bool p2 = (tid < 140);
    const int  p2f = tid / 28;
    const int  p2rem = tid - p2f * 28;
    const int  p2seg = p2rem / 7, p2col = p2rem - p2seg * 7;
    // phase3 role: 112 groups
    const bool p3 = (tid < 112);

    const float4* I4 = (const float4*)I;
    const float4* J4 = (const float4*)J;

    const __half2 z2 = __float2half2_rn(0.f);
    __half2 acc[10];
#pragma unroll
    for (int k = 0; k < 10; k++) acc[k] = z2;
    float ccacc = 0.f;

    // ---- prologue: load plane dout0-4 into sRaw ----
    {
        const int dp = dout0 - 4;
        float4 a = make_float4(0.f,0.f,0.f,0.f), b = a;
        if (inb && dp >= 0) {
            const unsigned q = (unsigned)dp * (HH * W4) + pq;
            a = I4[q]; b = J4[q];
        }
        if (ldr) {
            *(float4*)&sRI[sroff] = a;
            *(float4*)&sRJ[sroff] = b;
        }
        __syncthreads();
    }

    for (int ip = 0; ip < NP; ip++) {
        const int dp = dout0 - 4 + ip;       // plane currently in sRaw
        const bool valid = (dp >= 0) && (dp < DD);
        const int slot5 = (ip % RING) * 5;

        // ---- A: prefetch next plane into registers ----
        const int dn = dp + 1;
        float4 na = make_float4(0.f,0.f,0.f,0.f), nb = na;
        if (inb && dn >= 0 && dn < DD) {
            const unsigned q = (unsigned)dn * (HH * W4) + pq;
            na = I4[q]; nb = J4[q];
        }

        // ---- B: W-sums of current raw plane -> sW ----
        if (valid && p1) {
            const int base = p1r * RSTF + 4 * p1g;
            float iv[12], jv[12];
            *(float4*)(iv)     = *(const float4*)&sRI[base];
            *(float4*)(iv + 4) = *(const float4*)&sRI[base + 4];
            *(float4*)(iv + 8) = *(const float4*)&sRI[base + 8];
            *(float4*)(jv)     = *(const float4*)&sRJ[base];
            *(float4*)(jv + 4) = *(const float4*)&sRJ[base + 4];
            *(float4*)(jv + 8) = *(const float4*)&sRJ[base + 8];

            float oi[4], oj[4], oi2[4], oj2[4], oij[4];
            float si=0.f, sj=0.f, si2=0.f, sj2=0.f, sij=0.f;
#pragma unroll
            for (int t = 0; t < 9; t++) {
                float x = iv[t], y = jv[t];
                si += x; sj += y; si2 += x*x; sj2 += y*y; sij += x*y;
            }
            oi[0]=si; oj[0]=sj; oi2[0]=si2; oj2[0]=sj2; oij[0]=sij;
#pragma unroll
            for (int k = 1; k < 4; k++) {
                float ia = iv[k+8], ir = iv[k-1];
                float ja = jv[k+8], jr = jv[k-1];
                si  += ia - ir;        sj  += ja - jr;
                si2 += ia*ia - ir*ir;  sj2 += ja*ja - jr*jr;
                sij += ia*ja - ir*jr;
                oi[k]=si; oj[k]=sj; oi2[k]=si2; oj2[k]=sj2; oij[k]=sij;
            }
            const int so = p1r * SST + p1g;
            U2H4 t0,t1,t2,t3,t4;
            t0.h[0]=__floats2half2_rn(oi[0],oi[1]);   t0.h[1]=__floats2half2_rn(oi[2],oi[3]);
            t1.h[0]=__floats2half2_rn(oj[0],oj[1]);   t1.h[1]=__floats2half2_rn(oj[2],oj[3]);
            t2.h[0]=__floats2half2_rn(oi2[0],oi2[1]); t2.h[1]=__floats2half2_rn(oi2[2],oi2[3]);
            t3.h[0]=__floats2half2_rn(oj2[0],oj2[1]); t3.h[1]=__floats2half2_rn(oj2[2],oj2[3]);
            t4.h[0]=__floats2half2_rn(oij[0],oij[1]); t4.h[1]=__floats2half2_rn(oij[2],oij[3]);
            sW[0*SW_F + so] = t0.u;
            sW[1*SW_F + so] = t1.u;
            sW[2*SW_F + so] = t2.u;
            sW[3*SW_F + so] = t3.u;
            sW[4*SW_F + so] = t4.u;
        }
        __syncthreads();

        // ---- C: H-sums -> ring slot ----
        if (p2) {
            uint2* rg = sRing + (slot5 + p2f) * 112;
            const int o0 = p2seg * 4;
            if (valid) {
                const uint2* sf = sW + p2f * SW_F + p2col;
                __half2 s0 = z2, s1 = z2;
#pragma unroll
                for (int t = 0; t < 9; t++) {
                    U2H4 v; v.u = sf[(o0 + t) * SST];
                    s0 = __hadd2(s0, v.h[0]); s1 = __hadd2(s1, v.h[1]);
                }
#pragma unroll
                for (int k = 0; k < 4; k++) {
                    U2H4 o; o.h[0] = s0; o.h[1] = s1;
                    rg[(o0 + k) * TG + p2col] = o.u;
                    if (k < 3) {
                        U2H4 va, vs;
                        va.u = sf[(o0 + k + 9) * SST];
                        vs.u = sf[(o0 + k) * SST];
                        s0 = __hadd2(__hsub2(s0, vs.h[0]), va.h[0]);
                        s1 = __hadd2(__hsub2(s1, vs.h[1]), va.h[1]);
                    }
                }
            } else {
                U2H4 o; o.h[0] = z2; o.h[1] = z2;
#pragma unroll
                for (int k = 0; k < 4; k++) rg[(o0 + k) * TG + p2col] = o.u;
            }
        }
        __syncthreads();

        // ---- D: D-window update + cc ----
        if (p3) {
            if (ip >= 9) {
                const int ss5 = ((ip - 9) % RING) * 5;
#pragma unroll
                for (int f = 0; f < 5; f++) {
                    U2H4 v; v.u = sRing[(ss5 + f) * 112 + tid];
                    acc[2*f]   = __hsub2(acc[2*f],   v.h[0]);
                    acc[2*f+1] = __hsub2(acc[2*f+1], v.h[1]);
                }
            }
#pragma unroll
            for (int f = 0; f < 5; f++) {
                U2H4 v; v.u = sRing[(slot5 + f) * 112 + tid];
                acc[2*f]   = __hadd2(acc[2*f],   v.h[0]);
                acc[2*f+1] = __hadd2(acc[2*f+1], v.h[1]);
            }
            if (ip >= 8) {
                float2 fI0=__half22float2(acc[0]), fI1=__half22float2(acc[1]);
                float2 fJ0=__half22float2(acc[2]), fJ1=__half22float2(acc[3]);
                float2 fA0=__half22float2(acc[4]), fA1=__half22float2(acc[5]);
                float2 fB0=__half22float2(acc[6]), fB1=__half22float2(acc[7]);
                float2 fC0=__half22float2(acc[8]), fC1=__half22float2(acc[9]);
                ccacc += cc1(fI0.x, fJ0.x, fA0.x, fB0.x, fC0.x);
                ccacc += cc1(fI0.y, fJ0.y, fA0.y, fB0.y, fC0.y);
                ccacc += cc1(fI1.x, fJ1.x, fA1.x, fB1.x, fC1.x);
                ccacc += cc1(fI1.y, fJ1.y, fA1.y, fB1.y, fC1.y);
            }
        }

        // ---- E: commit prefetched raw plane to sRaw ----
        if (ldr) {
            *(float4*)&sRI[sroff] = na;
            *(float4*)&sRJ[sroff] = nb;
        }
        __syncthreads();
    }

    // ---- reduce + atomic ----
#pragma unroll
    for (int o = 16; o > 0; o >>= 1) ccacc += __shfl_xor_sync(0xFFFFFFFFu, ccacc, o);
    if ((tid & 31) == 0) wred[tid >> 5] = ccacc;
    __syncthreads();
    if (tid == 0) {
        float s = 0.f;
#pragma unroll
        for (int i = 0; i < 8; i++) s += wred[i];
        atomicAdd(out, -s * (1.0f / (float)VV));
    }
}

__global__ void zout(float* out) { out[0] = 0.f; }

// ---------------------------------------------------------------------------
extern "C" void kernel_launch(void* const* d_in, const int* in_sizes, int n_in,
                              void* d_out, int out_size) {
    const float* I = (const float*)d_in[0];
    const float* J = (const float*)d_in[1];
    float* out = (float*)d_out;

    cudaFuncSetAttribute(fused, cudaFuncAttributeMaxDynamicSharedMemorySize,
                         SMEM_BYTES);
    zout<<<1, 1>>>(out);
    fused<<<dim3(8, 12, 4), 256, SMEM_BYTES>>>(I, J, out);
}

// round 10
// speedup vs baseline: 1.3573x; 1.3573x over previous
#include <cuda_runtime.h>
#include <cuda_fp16.h>

#define DD 160
#define HH 192
#define WW 224
#define VV (DD*HH*WW)        // 6881280
#define W4 (WW/4)            // 56 float4 per input row
#define WU2 (WW/4)           // 56 uint2 (4-half) per row
#define VU2 (VV/4)           // uint2 elems per field = 1720320
#define PL2 (HH*WW/4)        // uint2 per d-plane = 10752

#define WC 56                // W outputs per block
#define HC 32                // H outputs per block
#define RH 40                // raw rows (HC + 8)
#define RST 68               // raw smem stride (uints = half2 voxels)
#define SST 15               // summed smem stride (uint2 per row)

// fp16 scratch: 5 fields x VV halves (68.8 MB) — WH-summed fields
__device__ __half g_B[5u * VV];

union U2H4 { uint2 u; __half2 h[2]; };
union U4H2 { uint4 u; __half2 h[4]; };

// ---------------------------------------------------------------------------
// Fused pass 1+2 (CHAMPION version): W-sum then H-sum, fp32 in, fp16 out.
// Raw tile held as packed half2(I,J) -> 34.9 KB smem -> 6 blocks/SM.
// ---------------------------------------------------------------------------
__global__ void __launch_bounds__(256) whpass(const float* __restrict__ I,
                                              const float* __restrict__ J,
                                              float* __restrict__ out) {
    __shared__ __align__(16) unsigned sR[RH * RST];  // 10.9 KB: half2(I,J)/voxel
    __shared__ __align__(16) uint2 sS[5 * RH * SST]; // 24 KB

    const int tid = threadIdx.x;
    const int w0  = blockIdx.x * WC;
    const int h0  = blockIdx.y * HC;
    const int d   = blockIdx.z;
    if (blockIdx.x == 0 && blockIdx.y == 0 && blockIdx.z == 0 && tid == 0)
        out[0] = 0.f;

    // ---- phase 0: load raw I,J tile rows [h0-4, h0+36), w [w0-4, w0+60) ----
    const int fb = (w0 - 4) >> 2;           // first float4 index (may be -1)
    const float4* I4 = (const float4*)I;
    const float4* J4 = (const float4*)J;
    for (int i = tid; i < RH * 16; i += 256) {
        const int r = i >> 4, c = i & 15;
        const int gh = h0 - 4 + r;
        const int gf = fb + c;
        float4 a = make_float4(0.f, 0.f, 0.f, 0.f);
        float4 b = a;
        if (gh >= 0 && gh < HH && gf >= 0 && gf < W4) {
            const size_t q = ((size_t)d * HH + gh) * W4 + gf;
            a = I4[q]; b = J4[q];
        }
        U4H2 t;
        t.h[0] = __floats2half2_rn(a.x, b.x);
        t.h[1] = __floats2half2_rn(a.y, b.y);
        t.h[2] = __floats2half2_rn(a.z, b.z);
        t.h[3] = __floats2half2_rn(a.w, b.w);
        *(uint4*)&sR[r * RST + 4 * c] = t.u;    // 16B aligned
    }
    __syncthreads();

    // ---- phase 1: W-sums (sliding 9-tap), 4 outputs/item, 5 fields -> sS ----
    for (int i = tid; i < 14 * RH; i += 256) {
        const int g = i / RH;              // output float4-group 0..13
        const int r = i - g * RH;          // row 0..39 (consecutive tids -> r)
        const int base = r * RST + 4 * g;  // 16B aligned

        float iv[12], jv[12];
        U4H2 q0, q1, q2;
        q0.u = *(const uint4*)&sR[base];
        q1.u = *(const uint4*)&sR[base + 4];
        q2.u = *(const uint4*)&sR[base + 8];
#pragma unroll
        for (int t = 0; t < 4; t++) {
            float2 v0 = __half22float2(q0.h[t]);
            float2 v1 = __half22float2(q1.h[t]);
            float2 v2 = __half22float2(q2.h[t]);
            iv[t] = v0.x;     jv[t] = v0.y;
            iv[t + 4] = v1.x; jv[t + 4] = v1.y;
            iv[t + 8] = v2.x; jv[t + 8] = v2.y;
        }

        float oi[4], oj[4], oi2[4], oj2[4], oij[4];
        float si=0.f, sj=0.f, si2=0.f, sj2=0.f, sij=0.f;
#pragma unroll
        for (int t = 0; t < 9; t++) {
            float x = iv[t], y = jv[t];
            si += x; sj += y; si2 += x*x; sj2 += y*y; sij += x*y;
        }
        oi[0]=si; oj[0]=sj; oi2[0]=si2; oj2[0]=sj2; oij[0]=sij;
#pragma unroll
        for (int k = 1; k < 4; k++) {
            float ia = iv[k+8], ir = iv[k-1];
            float ja = jv[k+8], jr = jv[k-1];
            si  += ia - ir;        sj  += ja - jr;
            si2 += ia*ia - ir*ir;  sj2 += ja*ja - jr*jr;
            sij += ia*ja - ir*jr;
            oi[k]=si; oj[k]=sj; oi2[k]=si2; oj2[k]=sj2; oij[k]=sij;
        }

        const int so = r * SST + g;
        U2H4 t0, t1, t2, t3, t4;
        t0.h[0]=__floats2half2_rn(oi[0],oi[1]);   t0.h[1]=__floats2half2_rn(oi[2],oi[3]);
        t1.h[0]=__floats2half2_rn(oj[0],oj[1]);   t1.h[1]=__floats2half2_rn(oj[2],oj[3]);
        t2.h[0]=__floats2half2_rn(oi2[0],oi2[1]); t2.h[1]=__floats2half2_rn(oi2[2],oi2[3]);
        t3.h[0]=__floats2half2_rn(oj2[0],oj2[1]); t3.h[1]=__floats2half2_rn(oj2[2],oj2[3]);
        t4.h[0]=__floats2half2_rn(oij[0],oij[1]); t4.h[1]=__floats2half2_rn(oij[2],oij[3]);
        sS[0*RH*SST + so] = t0.u;
        sS[1*RH*SST + so] = t1.u;
        sS[2*RH*SST + so] = t2.u;
        sS[3*RH*SST + so] = t3.u;
        sS[4*RH*SST + so] = t4.u;
    }
    __syncthreads();

    // ---- phase 2: H-sums (running window over sS rows) -> g_B --------------
    if (tid < 224) {
        const int col  = tid % 14;          // uint2 column in tile
        const int rest = tid / 14;          // 0..15
        const int seg  = rest & 7;          // 4-row segment
        const int grp  = rest >> 3;         // 0: fields 0-2, 1: fields 3-4
        const int f0 = grp ? 3 : 0;
        const int f1 = grp ? 5 : 3;
        const int o0 = seg * 4;             // local output row base

        uint2* Bg = (uint2*)g_B;
        for (int f = f0; f < f1; f++) {
            const uint2* sf = &sS[f * RH * SST];
            __half2 s0 = __float2half2_rn(0.f), s1 = s0;
#pragma unroll
            for (int t = 0; t < 9; t++) {        // taps lr = o0 .. o0+8
                U2H4 v; v.u = sf[(o0 + t) * SST + col];
                s0 = __hadd2(s0, v.h[0]); s1 = __hadd2(s1, v.h[1]);
            }
            const size_t fbase = (size_t)f * VU2 + blockIdx.x * 14 + col;
#pragma unroll
            for (int k = 0; k < 4; k++) {
                U2H4 o; o.h[0] = s0; o.h[1] = s1;
                Bg[fbase + ((size_t)d * HH + h0 + o0 + k) * WU2] = o.u;
                if (k < 3) {
                    U2H4 va, vs;
                    va.u = sf[(o0 + k + 9) * SST + col];
                    vs.u = sf[(o0 + k) * SST + col];
                    s0 = __hadd2(__hsub2(s0, vs.h[0]), va.h[0]);
                    s1 = __hadd2(__hsub2(s1, vs.h[1]), va.h[1]);
                }
            }
        }
    }
}

// ---------------------------------------------------------------------------
// Pass 3: along D. Chunk 16, explicit 2-plane batching: 20 loads in flight
// per stall period (double MLP), half the stall periods per voxel.
// ---------------------------------------------------------------------------
__device__ __forceinline__ float cc1(float si, float sj, float si2, float sj2, float sij) {
    const float inv = 1.0f / 729.0f;
    float cross = sij - si * sj * inv;
    float ivar  = si2 - si * si * inv;
    float jvar  = sj2 - sj * sj * inv;
    return __fdividef(cross * cross, ivar * jvar + 1e-5f);
}

__global__ void __launch_bounds__(256) dpass(float* __restrict__ out) {
    const int tid = threadIdx.x;
    const int col = blockIdx.x * 256 + tid;      // uint2 index within plane
    const int d0  = blockIdx.y * 16;
    const uint2* B = (const uint2*)g_B;

    __half2 z2 = __float2half2_rn(0.f);
    __half2 aI0=z2, aI1=z2, aJ0=z2, aJ1=z2, aI20=z2, aI21=z2,
            aJ20=z2, aJ21=z2, aIJ0=z2, aIJ1=z2;

#define LOADTAP(dst, cond, dp) { \
    if (cond) { const unsigned q_ = (unsigned)(dp) * PL2 + col; \
        dst[0].u = B[0u*VU2 + q_]; dst[1].u = B[1u*VU2 + q_]; \
        dst[2].u = B[2u*VU2 + q_]; dst[3].u = B[3u*VU2 + q_]; \
        dst[4].u = B[4u*VU2 + q_]; } \
    else { uint2 z = make_uint2(0u, 0u); \
        dst[0].u = z; dst[1].u = z; dst[2].u = z; dst[3].u = z; dst[4].u = z; } }

#define APPLY(v, HOP) { \
    aI0  = HOP(aI0,  v[0].h[0]); aI1  = HOP(aI1,  v[0].h[1]); \
    aJ0  = HOP(aJ0,  v[1].h[0]); aJ1  = HOP(aJ1,  v[1].h[1]); \
    aI20 = HOP(aI20, v[2].h[0]); aI21 = HOP(aI21, v[2].h[1]); \
    aJ20 = HOP(aJ20, v[3].h[0]); aJ21 = HOP(aJ21, v[3].h[1]); \
    aIJ0 = HOP(aIJ0, v[4].h[0]); aIJ1 = HOP(aIJ1, v[4].h[1]); }

#define CCEMIT { \
    float2 fI0=__half22float2(aI0),  fI1=__half22float2(aI1); \
    float2 fJ0=__half22float2(aJ0),  fJ1=__half22float2(aJ1); \
    float2 fA0=__half22float2(aI20), fA1=__half22float2(aI21); \
    float2 fB0=__half22float2(aJ20), fB1=__half22float2(aJ21); \
    float2 fC0=__half22float2(aIJ0), fC1=__half22float2(aIJ1); \
    acc += cc1(fI0.x, fJ0.x, fA0.x, fB0.x, fC0.x); \
    acc += cc1(fI0.y, fJ0.y, fA0.y, fB0.y, fC0.y); \
    acc += cc1(fI1.x, fJ1.x, fA1.x, fB1.x, fC1.x); \
    acc += cc1(fI1.y, fJ1.y, fA1.y, fB1.y, fC1.y); }

    // prologue: window for plane d0 (taps d0-4 .. d0+4)
#pragma unroll
    for (int t = -4; t <= 4; t++) {
        int dt = d0 + t;                          // d0+4 <= 148 < 160 always
        if (dt >= 0) {
            U2H4 v[5];
            LOADTAP(v, true, dt);
            APPLY(v, __hadd2);
        }
    }

    float acc = 0.f;
#pragma unroll 2
    for (int dd = 0; dd < 16; dd += 2) {
        const int d = d0 + dd;
        U2H4 va[5], vs[5], wa[5], ws[5];
        LOADTAP(va, (d + 5) < DD, d + 5);
        LOADTAP(vs, (d - 4) >= 0, d - 4);
        LOADTAP(wa, (d + 6) < DD, d + 6);
        LOADTAP(ws, (d - 3) >= 0, d - 3);
        CCEMIT;                       // plane d
        APPLY(va, __hadd2);
        APPLY(vs, __hsub2);
        CCEMIT;                       // plane d+1
        APPLY(wa, __hadd2);
        APPLY(ws, __hsub2);
    }
#undef LOADTAP
#undef APPLY
#undef CCEMIT

    // block reduction
#pragma unroll
    for (int o = 16; o > 0; o >>= 1) acc += __shfl_xor_sync(0xFFFFFFFFu, acc, o);
    __shared__ float wsum[8];
    if ((tid & 31) == 0) wsum[tid >> 5] = acc;
    __syncthreads();
    if (tid == 0) {
        float s = 0.f;
#pragma unroll
        for (int i = 0; i < 8; i++) s += wsum[i];
        atomicAdd(out, -s * (1.0f / (float)VV));
    }
}

// ---------------------------------------------------------------------------
extern "C" void kernel_launch(void* const* d_in, const int* in_sizes, int n_in,
                              void* d_out, int out_size) {
    const float* I = (const float*)d_in[0];
    const float* J = (const float*)d_in[1];
    float* out = (float*)d_out;

    whpass<<<dim3(4, 6, DD), 256>>>(I, J, out);  // 4 W x 6 H x 160 d
    dpass<<<dim3(42, 10), 256>>>(out);           // 10752 u2-cols / 256, 10 D-chunks
}